// round 12
// baseline (speedup 1.0000x reference)
#include <cuda_runtime.h>

#define NN 50000
#define NE 800000
#define NG 64
#define NBLK 196   // ceil(NN/256)
#define CAP 96     // bucket capacity per node (Poisson(16) degree; validated by rel_err)
#define LRELU(x) ((x) > 0.f ? (x) : 0.2f*(x))

// packed f32x2 fma: d = a*b + d   (2 MACs, one FMA-pipe slot)
#define FMA_F32X2(d, a, b) \
    asm("fma.rn.f32x2 %0, %1, %2, %0;" : "+l"(d) : "l"(a), "l"(b))
#define PACKF2(out, lo, hi) \
    asm("mov.b64 %0, {%1, %2};" : "=l"(out) : "f"(lo), "f"(hi))
#define UNPACKF2(lo, hi, in) \
    asm("mov.b64 {%0, %1}, %2;" : "=f"(lo), "=f"(hi) : "l"(in))

// ---------------- workspaces (static __device__, no allocation) ----------------
__device__ float d_c1[4];                      // cl0, cl1, cr0, cr1
__device__ int   d_cnt[NN];
__device__ int   d_adjB[NN*CAP];               // bucket adjacency: src ids grouped by dst
__device__ __align__(8)  float2 d_t1[NN];      // layer1 per-node {t0,t1}
__device__ __align__(16) float d_feat2[NN*32];
__device__ __align__(16) float d_res2p[NN*32];
__device__ float d_el2[NN];
__device__ float d_er2[NN];
__device__ __align__(16) float d_h2[NN*32];

// ---------------- init: zero bucket counters + layer1 attention constants --------------
__global__ void k_init(const float* __restrict__ W1, const float* __restrict__ al1,
                       const float* __restrict__ ar1) {
    int i = blockIdx.x*256 + threadIdx.x;
    if (i < NN) d_cnt[i] = 0;
    if (blockIdx.x == 0) {
        __shared__ float sl[128], sr[128];
        int t = threadIdx.x;
        if (t < 128) {
            float w = W1[t];
            sl[t] = w * al1[t];
            sr[t] = w * ar1[t];
        }
        __syncthreads();
        for (int off = 32; off > 0; off >>= 1) {
            if (t < 128 && (t & 63) < off) { sl[t] += sl[t+off]; sr[t] += sr[t+off]; }
            __syncthreads();
        }
        if (t < 128 && (t & 63) == 0) { d_c1[t>>6] = sl[t]; d_c1[2 + (t>>6)] = sr[t]; }
    }
}

// ---------------- bucket fill: 4 edges/thread (int4 loads, 4 independent chains) -------
__global__ void k_fillB(const int* __restrict__ src, const int* __restrict__ dst) {
    int t = blockIdx.x*blockDim.x + threadIdx.x;
    if (t >= NE/4) return;
    int4 d4 = ((const int4*)dst)[t];
    int4 s4 = ((const int4*)src)[t];
    int p0 = atomicAdd(&d_cnt[d4.x], 1);
    int p1 = atomicAdd(&d_cnt[d4.y], 1);
    int p2 = atomicAdd(&d_cnt[d4.z], 1);
    int p3 = atomicAdd(&d_cnt[d4.w], 1);
    d_adjB[d4.x*CAP + p0] = s4.x;
    d_adjB[d4.y*CAP + p1] = s4.y;
    d_adjB[d4.z*CAP + p2] = s4.z;
    d_adjB[d4.w*CAP + p3] = s4.w;
}

// ---------------- layer1 gather: per-node softmax sums -> t0,t1 (8 lanes/node) ---------
__global__ void k_e1g(const float* __restrict__ feat) {
    int t = blockIdx.x*blockDim.x + threadIdx.x;
    int node = t >> 3;
    int q = t & 7;
    bool valid = node < NN;
    int nn = valid ? node : 0;
    int cnt = valid ? d_cnt[nn] : 0;
    int base = nn*CAP;
    float fd = feat[nn];
    float B0 = d_c1[2]*fd, B1 = d_c1[3]*fd;
    float c0 = d_c1[0],   c1v = d_c1[1];
    float s0 = 0.f, n0 = 0.f, s1 = 0.f, n1 = 0.f;
    for (int j = q; j < cnt; j += 8) {
        int s = d_adjB[base + j];
        float fs = feat[s];
        float e0 = LRELU(fmaf(c0,  fs, B0));
        float e1 = LRELU(fmaf(c1v, fs, B1));
        float a0 = __expf(e0), a1 = __expf(e1);
        s0 += a0; n0 = fmaf(a0, fs, n0);
        s1 += a1; n1 = fmaf(a1, fs, n1);
    }
    #pragma unroll
    for (int o = 4; o > 0; o >>= 1) {
        s0 += __shfl_xor_sync(0xffffffffu, s0, o);
        n0 += __shfl_xor_sync(0xffffffffu, n0, o);
        s1 += __shfl_xor_sync(0xffffffffu, s1, o);
        n1 += __shfl_xor_sync(0xffffffffu, n1, o);
    }
    if (valid && q == 0) {
        float t0 = s0 > 0.f ? __fdividef(n0, s0) : 0.f;
        float t1 = s1 > 0.f ? __fdividef(n1, s1) : 0.f;
        d_t1[node] = make_float2(t0, t1);
    }
}

// ---------------- node kernel 1: 8 nodes/warp, 256 threads, 64KB dynamic smem ----------
// 8 warps share sWR (32KB); each warp has private sH (4KB). 3 blocks/SM -> 24 warps/SM.
__global__ void __launch_bounds__(256) k_node1(
    const float* __restrict__ feat, const float* __restrict__ W1,
    const float* __restrict__ res1, const float* __restrict__ b1,
    const float* __restrict__ g1g, const float* __restrict__ g1b,
    const float* __restrict__ g1m, const float* __restrict__ g1v,
    const float* __restrict__ W2, const float* __restrict__ res2,
    const float* __restrict__ al2, const float* __restrict__ ar2)
{
    extern __shared__ __align__(16) char dynsmem[];
    float2* sWR = (float2*)dynsmem;                               // 4096 float2 = 32KB
    int tid = threadIdx.x;
    int lane = tid & 31;
    int warp = tid >> 5;
    float2* sHw = (float2*)(dynsmem + 32768 + warp*4096);         // 512 float2 per warp

    for (int i = tid; i < 4096; i += 256) sWR[i] = make_float2(W2[i], res2[i]);

    float Pq[4], Qq[4], Rq[4];
    #pragma unroll
    for (int q = 0; q < 4; q++) {
        int hd = lane + 32*q;
        float sc = g1g[hd] * rsqrtf(g1v[hd] + 1e-5f);
        Pq[q] = W1[hd]  * sc;
        Qq[q] = res1[hd]* sc;
        Rq[q] = fmaf(b1[hd] - g1m[hd], sc, g1b[hd]);
    }
    float al2l = al2[lane], ar2l = ar2[lane];
    __syncthreads();

    int wid  = blockIdx.x*8 + warp;
    int nwarp = gridDim.x*8;

    for (int base = wid*8; base < NN; base += nwarp*8) {   // NN = 8*6250, no tail
        // per-lane node data for node = base + (lane&7), broadcast to all lanes
        int nl = base + (lane & 7);
        float f_l = feat[nl];
        float2 tt_l = d_t1[nl];
        float fm[8], t0m[8], t1m[8];
        #pragma unroll
        for (int m = 0; m < 8; m++) {
            fm[m]  = __shfl_sync(0xffffffffu, f_l,    m);
            t0m[m] = __shfl_sync(0xffffffffu, tt_l.x, m);
            t1m[m] = __shfl_sync(0xffffffffu, tt_l.y, m);
        }
        // phase A: lane owns k = lane + 32q; store packed node-pairs
        #pragma unroll
        for (int q = 0; q < 4; q++) {
            int k = lane + 32*q;
            #pragma unroll
            for (int p = 0; p < 4; p++) {
                float ta = (q < 2) ? t0m[2*p]   : t1m[2*p];
                float tb = (q < 2) ? t0m[2*p+1] : t1m[2*p+1];
                float ha = fmaxf(fmaf(Pq[q], ta, fmaf(Qq[q], fm[2*p],   Rq[q])), 0.f);
                float hb = fmaxf(fmaf(Pq[q], tb, fmaf(Qq[q], fm[2*p+1], Rq[q])), 0.f);
                sHw[k*4 + p] = make_float2(ha, hb);
            }
        }
        __syncwarp();

        // phase B: dual GEMV, 8 nodes, packed f32x2 accumulators
        unsigned long long F[4] = {0,0,0,0}, Rr[4] = {0,0,0,0};
        #pragma unroll 8
        for (int k = 0; k < 128; k++) {
            ulonglong2 hA = *(const ulonglong2*)&sHw[k*4];      // pairs (n0,n1),(n2,n3)
            ulonglong2 hB = *(const ulonglong2*)&sHw[k*4 + 2];  // pairs (n4,n5),(n6,n7)
            float2 wr = sWR[k*32 + lane];
            unsigned long long ww, rr;
            PACKF2(ww, wr.x, wr.x);
            PACKF2(rr, wr.y, wr.y);
            FMA_F32X2(F[0],  hA.x, ww);
            FMA_F32X2(F[1],  hA.y, ww);
            FMA_F32X2(F[2],  hB.x, ww);
            FMA_F32X2(F[3],  hB.y, ww);
            FMA_F32X2(Rr[0], hA.x, rr);
            FMA_F32X2(Rr[1], hA.y, rr);
            FMA_F32X2(Rr[2], hB.x, rr);
            FMA_F32X2(Rr[3], hB.y, rr);
        }
        __syncwarp();

        float f2[8], r2[8];
        #pragma unroll
        for (int p = 0; p < 4; p++) {
            UNPACKF2(f2[2*p], f2[2*p+1], F[p]);
            UNPACKF2(r2[2*p], r2[2*p+1], Rr[p]);
        }

        #pragma unroll
        for (int m = 0; m < 8; m++) {
            int n = base + m;
            d_feat2[n*32 + lane] = f2[m];
            d_res2p[n*32 + lane] = r2[m];
            float vl = f2[m]*al2l, vr = f2[m]*ar2l;
            #pragma unroll
            for (int o = 16; o > 0; o >>= 1) {
                vl += __shfl_xor_sync(0xffffffffu, vl, o);
                vr += __shfl_xor_sync(0xffffffffu, vr, o);
            }
            if (lane == 0) { d_el2[n] = vl; d_er2[n] = vr; }
        }
    }
}

// ---------------- layer2 gather + h2/BN2/ReLU (warp per node, serial-shfl; measured-good)
__global__ void __launch_bounds__(256) k_e2h(
    const float* __restrict__ b2,
    const float* __restrict__ g2g, const float* __restrict__ g2b,
    const float* __restrict__ g2m, const float* __restrict__ g2v)
{
    int tid = threadIdx.x;
    int lane = tid & 31;
    int node = blockIdx.x*8 + (tid >> 5);    // grid 6250 -> exactly 50000 warps
    float sc2l = g2g[lane] * rsqrtf(g2v[lane] + 1e-5f);
    float sh2l = g2b[lane] - g2m[lane]*sc2l;
    float b2l  = b2[lane];

    int cnt = d_cnt[node];
    int base = node*CAP;
    float erd = d_er2[node];
    float acc = 0.f, la = 0.f;

    for (int c = 0; c < cnt; c += 32) {
        int j = c + lane;
        float a = 0.f; int sj = 0;
        if (j < cnt) {
            sj = d_adjB[base + j];
            float ev = LRELU(d_el2[sj] + erd);
            a = __expf(ev);
            la += a;
        }
        int m = min(32, cnt - c);
        for (int k = 0; k < m; k++) {
            float ak = __shfl_sync(0xffffffffu, a, k);
            int   sk = __shfl_sync(0xffffffffu, sj, k);
            acc = fmaf(ak, d_feat2[sk*32 + lane], acc);
        }
    }
    #pragma unroll
    for (int o = 16; o > 0; o >>= 1) la += __shfl_xor_sync(0xffffffffu, la, o);

    float x = (la > 0.f ? __fdividef(acc, la) : 0.f) + d_res2p[node*32 + lane] + b2l;
    d_h2[node*32 + lane] = fmaxf(fmaf(x, sc2l, sh2l), 0.f);
}

// ---------------- decoder (4 nodes/warp) + merged graph mean-pool ----------------------
// Blocks [0,888): decoder. Blocks [888, 888+NG): pool for graph g = blockIdx-888.
__global__ void __launch_bounds__(256) k_node2d(
    const float* __restrict__ Wd1, const float* __restrict__ bd1,
    const float* __restrict__ gdg, const float* __restrict__ gdb,
    const float* __restrict__ gdm, const float* __restrict__ gdv,
    const float* __restrict__ Wd2, const float* __restrict__ bd2,
    const int* __restrict__ gids, float* __restrict__ out)
{
    int tid = threadIdx.x;
    int lane = tid & 31;

    if (blockIdx.x >= 888) {
        // ---- graph mean-pool (graph_ids sorted; binary-search bounds) ----
        int g = blockIdx.x - 888;
        int a = 0, b = NN;
        while (a < b) { int mid = (a+b) >> 1; if (gids[mid] < g) a = mid+1; else b = mid; }
        int lo = a;
        a = lo; b = NN;
        while (a < b) { int mid = (a+b) >> 1; if (gids[mid] < g+1) a = mid+1; else b = mid; }
        int hi = a;

        __shared__ float sacc[256];
        int grp = tid >> 5;
        float acc = 0.f;
        for (int n = lo + grp; n < hi; n += 8) acc += d_h2[n*32 + lane];
        sacc[tid] = acc;
        __syncthreads();
        if (tid < 128) sacc[tid] += sacc[tid + 128];
        __syncthreads();
        if (tid < 64)  sacc[tid] += sacc[tid + 64];
        __syncthreads();
        if (tid < 32) {
            float v = sacc[tid] + sacc[tid + 32];
            float cnt = (float)(hi - lo);
            out[g*32 + tid] = v / fmaxf(cnt, 1.f);
        }
        return;
    }

    __shared__ float4 sW4[32*32];   // Wd1 reordered: [k][lane] -> cols {lane,+32,+64,+96}
    for (int i = tid; i < 1024; i += 256) {
        int k = i >> 5, l = i & 31;
        sW4[i] = make_float4(Wd1[k*128 + l], Wd1[k*128 + l + 32],
                             Wd1[k*128 + l + 64], Wd1[k*128 + l + 96]);
    }
    float scd[4], shd[4], wd2l[4];
    #pragma unroll
    for (int j = 0; j < 4; j++) {
        int c = lane + 32*j;
        float sc = gdg[c] * rsqrtf(gdv[c] + 1e-5f);
        scd[j] = sc;
        shd[j] = fmaf(bd1[c] - gdm[c], sc, gdb[c]);
        wd2l[j] = Wd2[c];
    }
    float bd2v = bd2[0];
    __syncthreads();

    int wid  = blockIdx.x*8 + (tid >> 5);
    int nwarp = 888*8;

    for (int base = wid*4; base < NN; base += nwarp*4) {
        float h2v[4];
        #pragma unroll
        for (int m = 0; m < 4; m++) h2v[m] = d_h2[(base + m)*32 + lane];

        float y[4][4] = {{0,0,0,0},{0,0,0,0},{0,0,0,0},{0,0,0,0}};
        #pragma unroll 8
        for (int k = 0; k < 32; k++) {
            float4 w4 = sW4[k*32 + lane];
            #pragma unroll
            for (int m = 0; m < 4; m++) {
                float hk = __shfl_sync(0xffffffffu, h2v[m], k);
                y[m][0] = fmaf(hk, w4.x, y[m][0]);
                y[m][1] = fmaf(hk, w4.y, y[m][1]);
                y[m][2] = fmaf(hk, w4.z, y[m][2]);
                y[m][3] = fmaf(hk, w4.w, y[m][3]);
            }
        }
        #pragma unroll
        for (int m = 0; m < 4; m++) {
            float acc = 0.f;
            #pragma unroll
            for (int j = 0; j < 4; j++)
                acc += fmaxf(fmaf(y[m][j], scd[j], shd[j]), 0.f) * wd2l[j];
            #pragma unroll
            for (int o = 16; o > 0; o >>= 1) acc += __shfl_xor_sync(0xffffffffu, acc, o);
            if (lane == 0) out[2048 + base + m] = acc + bd2v;
        }
    }
}

// ---------------- launch ----------------
extern "C" void kernel_launch(void* const* d_in, const int* in_sizes, int n_in,
                              void* d_out, int out_size) {
    const float* feat = (const float*)d_in[0];
    const float* W1   = (const float*)d_in[1];
    const float* al1  = (const float*)d_in[2];
    const float* ar1  = (const float*)d_in[3];
    const float* res1 = (const float*)d_in[4];
    const float* b1   = (const float*)d_in[5];
    const float* g1g  = (const float*)d_in[6];
    const float* g1b  = (const float*)d_in[7];
    const float* g1m  = (const float*)d_in[8];
    const float* g1v  = (const float*)d_in[9];
    const float* W2   = (const float*)d_in[10];
    const float* al2  = (const float*)d_in[11];
    const float* ar2  = (const float*)d_in[12];
    const float* res2 = (const float*)d_in[13];
    const float* b2   = (const float*)d_in[14];
    const float* g2g  = (const float*)d_in[15];
    const float* g2b  = (const float*)d_in[16];
    const float* g2m  = (const float*)d_in[17];
    const float* g2v  = (const float*)d_in[18];
    const float* Wd1  = (const float*)d_in[19];
    const float* bd1  = (const float*)d_in[20];
    const float* gdg  = (const float*)d_in[21];
    const float* gdb  = (const float*)d_in[22];
    const float* gdm  = (const float*)d_in[23];
    const float* gdv  = (const float*)d_in[24];
    const float* Wd2  = (const float*)d_in[25];
    const float* bd2  = (const float*)d_in[26];
    const int* src    = (const int*)d_in[27];
    const int* dst    = (const int*)d_in[28];
    const int* gids   = (const int*)d_in[29];
    float* out = (float*)d_out;

    cudaFuncSetAttribute(k_node1, cudaFuncAttributeMaxDynamicSharedMemorySize, 65536);

    k_init<<<NBLK, 256>>>(W1, al1, ar1);
    k_fillB<<<(NE/4 + 255)/256, 256>>>(src, dst);
    k_e1g<<<(NN*8 + 255)/256, 256>>>(feat);
    k_node1<<<592, 256, 65536>>>(feat, W1, res1, b1, g1g, g1b, g1m, g1v, W2, res2, al2, ar2);
    k_e2h<<<NN/8, 256>>>(b2, g2g, g2b, g2m, g2v);
    k_node2d<<<888 + NG, 256>>>(Wd1, bd1, gdg, gdb, gdm, gdv, Wd2, bd2, gids, out);
}

// round 13
// speedup vs baseline: 1.0025x; 1.0025x over previous
#include <cuda_runtime.h>

#define NN 50000
#define NE 800000
#define NG 64
#define CAP 96     // bucket capacity per node (Poisson(16) degree; validated by rel_err)
#define LRELU(x) ((x) > 0.f ? (x) : 0.2f*(x))

// packed f32x2 fma: d = a*b + d   (2 MACs, one FMA-pipe slot)
#define FMA_F32X2(d, a, b) \
    asm("fma.rn.f32x2 %0, %1, %2, %0;" : "+l"(d) : "l"(a), "l"(b))
#define PACKF2(out, lo, hi) \
    asm("mov.b64 %0, {%1, %2};" : "=l"(out) : "f"(lo), "f"(hi))
#define UNPACKF2(lo, hi, in) \
    asm("mov.b64 {%0, %1}, %2;" : "=f"(lo), "=f"(hi) : "l"(in))

// ---------------- workspaces (static __device__, zero-initialized; no allocation) -------
__device__ float d_c1[4];                      // cl0, cl1, cr0, cr1
__device__ int   d_cnt[NN];                    // zeroed by e2h at end of each run
__device__ int   d_adjB[NN*CAP];               // bucket adjacency: src ids grouped by dst
__device__ __align__(8)  float2 d_t1[NN];      // layer1 per-node {t0,t1}
__device__ __align__(16) float d_feat2[NN*32];
__device__ __align__(16) float d_res2p[NN*32];
__device__ float d_el2[NN];
__device__ float d_er2[NN];
__device__ __align__(16) float d_h2[NN*32];

// ---------------- bucket fill (4 edges/thread, int4) + layer1 attn constants (block 0) --
__global__ void k_fillB(const int* __restrict__ src, const int* __restrict__ dst,
                        const float* __restrict__ W1, const float* __restrict__ al1,
                        const float* __restrict__ ar1) {
    // block 0: compute cl/cr constants (consumed by NEXT kernel, no intra-kernel order)
    if (blockIdx.x == 0) {
        __shared__ float sl[128], sr[128];
        int t = threadIdx.x;
        if (t < 128) {
            float w = W1[t];
            sl[t] = w * al1[t];
            sr[t] = w * ar1[t];
        }
        __syncthreads();
        for (int off = 32; off > 0; off >>= 1) {
            if (t < 128 && (t & 63) < off) { sl[t] += sl[t+off]; sr[t] += sr[t+off]; }
            __syncthreads();
        }
        if (t < 128 && (t & 63) == 0) { d_c1[t>>6] = sl[t]; d_c1[2 + (t>>6)] = sr[t]; }
    }
    int t = blockIdx.x*blockDim.x + threadIdx.x;
    if (t >= NE/4) return;
    int4 d4 = ((const int4*)dst)[t];
    int4 s4 = ((const int4*)src)[t];
    int p0 = atomicAdd(&d_cnt[d4.x], 1);
    int p1 = atomicAdd(&d_cnt[d4.y], 1);
    int p2 = atomicAdd(&d_cnt[d4.z], 1);
    int p3 = atomicAdd(&d_cnt[d4.w], 1);
    d_adjB[d4.x*CAP + p0] = s4.x;
    d_adjB[d4.y*CAP + p1] = s4.y;
    d_adjB[d4.z*CAP + p2] = s4.z;
    d_adjB[d4.w*CAP + p3] = s4.w;
}

// ---------------- layer1 gather: per-node softmax sums -> t0,t1 (8 lanes/node) ---------
__global__ void k_e1g(const float* __restrict__ feat) {
    int t = blockIdx.x*blockDim.x + threadIdx.x;
    int node = t >> 3;
    int q = t & 7;
    bool valid = node < NN;
    int nn = valid ? node : 0;
    int cnt = valid ? d_cnt[nn] : 0;
    int base = nn*CAP;
    float fd = feat[nn];
    float B0 = d_c1[2]*fd, B1 = d_c1[3]*fd;
    float c0 = d_c1[0],   c1v = d_c1[1];
    float s0 = 0.f, n0 = 0.f, s1 = 0.f, n1 = 0.f;
    for (int j = q; j < cnt; j += 8) {
        int s = d_adjB[base + j];
        float fs = feat[s];
        float e0 = LRELU(fmaf(c0,  fs, B0));
        float e1 = LRELU(fmaf(c1v, fs, B1));
        float a0 = __expf(e0), a1 = __expf(e1);
        s0 += a0; n0 = fmaf(a0, fs, n0);
        s1 += a1; n1 = fmaf(a1, fs, n1);
    }
    #pragma unroll
    for (int o = 4; o > 0; o >>= 1) {
        s0 += __shfl_xor_sync(0xffffffffu, s0, o);
        n0 += __shfl_xor_sync(0xffffffffu, n0, o);
        s1 += __shfl_xor_sync(0xffffffffu, s1, o);
        n1 += __shfl_xor_sync(0xffffffffu, n1, o);
    }
    if (valid && q == 0) {
        float t0 = s0 > 0.f ? __fdividef(n0, s0) : 0.f;
        float t1 = s1 > 0.f ? __fdividef(n1, s1) : 0.f;
        d_t1[node] = make_float2(t0, t1);
    }
}

// ---------------- node kernel 1: 8 nodes/warp, packed-pair smem transpose, FFMA2 -------
// Block = 128 threads (4 warps). smem = 32KB sWR + 16KB sH = 48KB. (R11 measured-good.)
__global__ void __launch_bounds__(128) k_node1(
    const float* __restrict__ feat, const float* __restrict__ W1,
    const float* __restrict__ res1, const float* __restrict__ b1,
    const float* __restrict__ g1g, const float* __restrict__ g1b,
    const float* __restrict__ g1m, const float* __restrict__ g1v,
    const float* __restrict__ W2, const float* __restrict__ res2,
    const float* __restrict__ al2, const float* __restrict__ ar2)
{
    __shared__ float2 sWR[4096];                        // {W2,res2} interleaved  32KB
    __shared__ __align__(16) float2 sH[4][128*4];       // per-warp [k][pair]     16KB
    int tid = threadIdx.x;
    for (int i = tid; i < 4096; i += 128) sWR[i] = make_float2(W2[i], res2[i]);

    int lane = tid & 31;
    int warp = tid >> 5;
    float2* sHw = sH[warp];

    float Pq[4], Qq[4], Rq[4];
    #pragma unroll
    for (int q = 0; q < 4; q++) {
        int hd = lane + 32*q;
        float sc = g1g[hd] * rsqrtf(g1v[hd] + 1e-5f);
        Pq[q] = W1[hd]  * sc;
        Qq[q] = res1[hd]* sc;
        Rq[q] = fmaf(b1[hd] - g1m[hd], sc, g1b[hd]);
    }
    float al2l = al2[lane], ar2l = ar2[lane];
    __syncthreads();

    int wid  = blockIdx.x*4 + warp;          // grid 1184 -> 4736 warps
    int nwarp = gridDim.x*4;

    for (int base = wid*8; base < NN; base += nwarp*8) {   // NN = 8*6250, no tail
        int nl = base + (lane & 7);
        float f_l = feat[nl];
        float2 tt_l = d_t1[nl];
        float fm[8], t0m[8], t1m[8];
        #pragma unroll
        for (int m = 0; m < 8; m++) {
            fm[m]  = __shfl_sync(0xffffffffu, f_l,    m);
            t0m[m] = __shfl_sync(0xffffffffu, tt_l.x, m);
            t1m[m] = __shfl_sync(0xffffffffu, tt_l.y, m);
        }
        // phase A: lane owns k = lane + 32q; store packed node-pairs
        #pragma unroll
        for (int q = 0; q < 4; q++) {
            int k = lane + 32*q;
            #pragma unroll
            for (int p = 0; p < 4; p++) {
                float ta = (q < 2) ? t0m[2*p]   : t1m[2*p];
                float tb = (q < 2) ? t0m[2*p+1] : t1m[2*p+1];
                float ha = fmaxf(fmaf(Pq[q], ta, fmaf(Qq[q], fm[2*p],   Rq[q])), 0.f);
                float hb = fmaxf(fmaf(Pq[q], tb, fmaf(Qq[q], fm[2*p+1], Rq[q])), 0.f);
                sHw[k*4 + p] = make_float2(ha, hb);
            }
        }
        __syncwarp();

        // phase B: dual GEMV, 8 nodes, packed f32x2 accumulators
        unsigned long long F[4] = {0,0,0,0}, Rr[4] = {0,0,0,0};
        #pragma unroll 8
        for (int k = 0; k < 128; k++) {
            ulonglong2 hA = *(const ulonglong2*)&sHw[k*4];      // pairs (n0,n1),(n2,n3)
            ulonglong2 hB = *(const ulonglong2*)&sHw[k*4 + 2];  // pairs (n4,n5),(n6,n7)
            float2 wr = sWR[k*32 + lane];
            unsigned long long ww, rr;
            PACKF2(ww, wr.x, wr.x);
            PACKF2(rr, wr.y, wr.y);
            FMA_F32X2(F[0],  hA.x, ww);
            FMA_F32X2(F[1],  hA.y, ww);
            FMA_F32X2(F[2],  hB.x, ww);
            FMA_F32X2(F[3],  hB.y, ww);
            FMA_F32X2(Rr[0], hA.x, rr);
            FMA_F32X2(Rr[1], hA.y, rr);
            FMA_F32X2(Rr[2], hB.x, rr);
            FMA_F32X2(Rr[3], hB.y, rr);
        }
        __syncwarp();

        float f2[8], r2[8];
        #pragma unroll
        for (int p = 0; p < 4; p++) {
            UNPACKF2(f2[2*p], f2[2*p+1], F[p]);
            UNPACKF2(r2[2*p], r2[2*p+1], Rr[p]);
        }

        #pragma unroll
        for (int m = 0; m < 8; m++) {
            int n = base + m;
            d_feat2[n*32 + lane] = f2[m];
            d_res2p[n*32 + lane] = r2[m];
            float vl = f2[m]*al2l, vr = f2[m]*ar2l;
            #pragma unroll
            for (int o = 16; o > 0; o >>= 1) {
                vl += __shfl_xor_sync(0xffffffffu, vl, o);
                vr += __shfl_xor_sync(0xffffffffu, vr, o);
            }
            if (lane == 0) { d_el2[n] = vl; d_er2[n] = vr; }
        }
    }
}

// ---------------- layer2 gather + h2/BN2/ReLU (warp/node) + self-cleaning cnt ----------
__global__ void __launch_bounds__(256) k_e2h(
    const float* __restrict__ b2,
    const float* __restrict__ g2g, const float* __restrict__ g2b,
    const float* __restrict__ g2m, const float* __restrict__ g2v)
{
    int tid = threadIdx.x;
    int lane = tid & 31;
    int node = blockIdx.x*8 + (tid >> 5);    // grid 6250 -> exactly 50000 warps
    float sc2l = g2g[lane] * rsqrtf(g2v[lane] + 1e-5f);
    float sh2l = g2b[lane] - g2m[lane]*sc2l;
    float b2l  = b2[lane];

    int cnt = d_cnt[node];
    int base = node*CAP;
    float erd = d_er2[node];
    float acc = 0.f, la = 0.f;

    for (int c = 0; c < cnt; c += 32) {
        int j = c + lane;
        float a = 0.f; int sj = 0;
        if (j < cnt) {
            sj = d_adjB[base + j];
            float ev = LRELU(d_el2[sj] + erd);
            a = __expf(ev);
            la += a;
        }
        int m = min(32, cnt - c);
        for (int k = 0; k < m; k++) {
            float ak = __shfl_sync(0xffffffffu, a, k);
            int   sk = __shfl_sync(0xffffffffu, sj, k);
            acc = fmaf(ak, d_feat2[sk*32 + lane], acc);
        }
    }
    #pragma unroll
    for (int o = 16; o > 0; o >>= 1) la += __shfl_xor_sync(0xffffffffu, la, o);

    float x = (la > 0.f ? __fdividef(acc, la) : 0.f) + d_res2p[node*32 + lane] + b2l;
    d_h2[node*32 + lane] = fmaxf(fmaf(x, sc2l, sh2l), 0.f);

    // self-clean: last consumer of d_cnt zeroes it for the next replay
    if (lane == 0) d_cnt[node] = 0;
}

// ---------------- decoder (4 nodes/warp) + merged graph mean-pool ----------------------
// Blocks [0,888): decoder. Blocks [888, 888+NG): pool for graph g = blockIdx-888.
__global__ void __launch_bounds__(256) k_node2d(
    const float* __restrict__ Wd1, const float* __restrict__ bd1,
    const float* __restrict__ gdg, const float* __restrict__ gdb,
    const float* __restrict__ gdm, const float* __restrict__ gdv,
    const float* __restrict__ Wd2, const float* __restrict__ bd2,
    const int* __restrict__ gids, float* __restrict__ out)
{
    int tid = threadIdx.x;
    int lane = tid & 31;

    if (blockIdx.x >= 888) {
        // ---- graph mean-pool (graph_ids sorted; binary-search bounds) ----
        int g = blockIdx.x - 888;
        int a = 0, b = NN;
        while (a < b) { int mid = (a+b) >> 1; if (gids[mid] < g) a = mid+1; else b = mid; }
        int lo = a;
        a = lo; b = NN;
        while (a < b) { int mid = (a+b) >> 1; if (gids[mid] < g+1) a = mid+1; else b = mid; }
        int hi = a;

        __shared__ float sacc[256];
        int grp = tid >> 5;
        float acc = 0.f;
        for (int n = lo + grp; n < hi; n += 8) acc += d_h2[n*32 + lane];
        sacc[tid] = acc;
        __syncthreads();
        if (tid < 128) sacc[tid] += sacc[tid + 128];
        __syncthreads();
        if (tid < 64)  sacc[tid] += sacc[tid + 64];
        __syncthreads();
        if (tid < 32) {
            float v = sacc[tid] + sacc[tid + 32];
            float cnt = (float)(hi - lo);
            out[g*32 + tid] = v / fmaxf(cnt, 1.f);
        }
        return;
    }

    __shared__ float4 sW4[32*32];   // Wd1 reordered: [k][lane] -> cols {lane,+32,+64,+96}
    for (int i = tid; i < 1024; i += 256) {
        int k = i >> 5, l = i & 31;
        sW4[i] = make_float4(Wd1[k*128 + l], Wd1[k*128 + l + 32],
                             Wd1[k*128 + l + 64], Wd1[k*128 + l + 96]);
    }
    float scd[4], shd[4], wd2l[4];
    #pragma unroll
    for (int j = 0; j < 4; j++) {
        int c = lane + 32*j;
        float sc = gdg[c] * rsqrtf(gdv[c] + 1e-5f);
        scd[j] = sc;
        shd[j] = fmaf(bd1[c] - gdm[c], sc, gdb[c]);
        wd2l[j] = Wd2[c];
    }
    float bd2v = bd2[0];
    __syncthreads();

    int wid  = blockIdx.x*8 + (tid >> 5);
    int nwarp = 888*8;

    for (int base = wid*4; base < NN; base += nwarp*4) {
        float h2v[4];
        #pragma unroll
        for (int m = 0; m < 4; m++) h2v[m] = d_h2[(base + m)*32 + lane];

        float y[4][4] = {{0,0,0,0},{0,0,0,0},{0,0,0,0},{0,0,0,0}};
        #pragma unroll 8
        for (int k = 0; k < 32; k++) {
            float4 w4 = sW4[k*32 + lane];
            #pragma unroll
            for (int m = 0; m < 4; m++) {
                float hk = __shfl_sync(0xffffffffu, h2v[m], k);
                y[m][0] = fmaf(hk, w4.x, y[m][0]);
                y[m][1] = fmaf(hk, w4.y, y[m][1]);
                y[m][2] = fmaf(hk, w4.z, y[m][2]);
                y[m][3] = fmaf(hk, w4.w, y[m][3]);
            }
        }
        #pragma unroll
        for (int m = 0; m < 4; m++) {
            float acc = 0.f;
            #pragma unroll
            for (int j = 0; j < 4; j++)
                acc += fmaxf(fmaf(y[m][j], scd[j], shd[j]), 0.f) * wd2l[j];
            #pragma unroll
            for (int o = 16; o > 0; o >>= 1) acc += __shfl_xor_sync(0xffffffffu, acc, o);
            if (lane == 0) out[2048 + base + m] = acc + bd2v;
        }
    }
}

// ---------------- launch ----------------
extern "C" void kernel_launch(void* const* d_in, const int* in_sizes, int n_in,
                              void* d_out, int out_size) {
    const float* feat = (const float*)d_in[0];
    const float* W1   = (const float*)d_in[1];
    const float* al1  = (const float*)d_in[2];
    const float* ar1  = (const float*)d_in[3];
    const float* res1 = (const float*)d_in[4];
    const float* b1   = (const float*)d_in[5];
    const float* g1g  = (const float*)d_in[6];
    const float* g1b  = (const float*)d_in[7];
    const float* g1m  = (const float*)d_in[8];
    const float* g1v  = (const float*)d_in[9];
    const float* W2   = (const float*)d_in[10];
    const float* al2  = (const float*)d_in[11];
    const float* ar2  = (const float*)d_in[12];
    const float* res2 = (const float*)d_in[13];
    const float* b2   = (const float*)d_in[14];
    const float* g2g  = (const float*)d_in[15];
    const float* g2b  = (const float*)d_in[16];
    const float* g2m  = (const float*)d_in[17];
    const float* g2v  = (const float*)d_in[18];
    const float* Wd1  = (const float*)d_in[19];
    const float* bd1  = (const float*)d_in[20];
    const float* gdg  = (const float*)d_in[21];
    const float* gdb  = (const float*)d_in[22];
    const float* gdm  = (const float*)d_in[23];
    const float* gdv  = (const float*)d_in[24];
    const float* Wd2  = (const float*)d_in[25];
    const float* bd2  = (const float*)d_in[26];
    const int* src    = (const int*)d_in[27];
    const int* dst    = (const int*)d_in[28];
    const int* gids   = (const int*)d_in[29];
    float* out = (float*)d_out;

    k_fillB<<<(NE/4 + 255)/256, 256>>>(src, dst, W1, al1, ar1);
    k_e1g<<<(NN*8 + 255)/256, 256>>>(feat);
    k_node1<<<1184, 128>>>(feat, W1, res1, b1, g1g, g1b, g1m, g1v, W2, res2, al2, ar2);
    k_e2h<<<NN/8, 256>>>(b2, g2g, g2b, g2m, g2v);
    k_node2d<<<888 + NG, 256>>>(Wd1, bd1, gdg, gdb, gdm, gdv, Wd2, bd2, gids, out);
}

// round 15
// speedup vs baseline: 1.0676x; 1.0649x over previous
#include <cuda_runtime.h>

#define NN 50000
#define NE 800000
#define NG 64
#define NBLK 196   // ceil(NN/256)
#define CAP 96     // bucket capacity per node (Poisson(16) degree; validated by rel_err)
#define LRELU(x) ((x) > 0.f ? (x) : 0.2f*(x))

// packed f32x2 fma: d = a*b + d   (2 MACs, one FMA-pipe slot)
#define FMA_F32X2(d, a, b) \
    asm("fma.rn.f32x2 %0, %1, %2, %0;" : "+l"(d) : "l"(a), "l"(b))
#define PACKF2(out, lo, hi) \
    asm("mov.b64 %0, {%1, %2};" : "=l"(out) : "f"(lo), "f"(hi))
#define UNPACKF2(lo, hi, in) \
    asm("mov.b64 {%0, %1}, %2;" : "=f"(lo), "=f"(hi) : "l"(in))

// ---------------- workspaces (static __device__, no allocation) ----------------
__device__ float d_c1[4];                      // cl0, cl1, cr0, cr1
__device__ int   d_cnt[NN];
__device__ int   d_adjB[NN*CAP];               // bucket adjacency: src ids grouped by dst
__device__ __align__(8)  float2 d_t1[NN];      // layer1 per-node {t0,t1}
__device__ __align__(16) float d_feat2[NN*32];
__device__ __align__(16) float d_res2p[NN*32];
__device__ float d_el2[NN];
__device__ float d_er2[NN];
__device__ __align__(16) float d_h2[NN*32];

// ---------------- init: zero bucket counters + layer1 attention constants --------------
__global__ void k_init(const float* __restrict__ W1, const float* __restrict__ al1,
                       const float* __restrict__ ar1) {
    int i = blockIdx.x*256 + threadIdx.x;
    if (i < NN) d_cnt[i] = 0;
    if (blockIdx.x == 0) {
        __shared__ float sl[128], sr[128];
        int t = threadIdx.x;
        if (t < 128) {
            float w = W1[t];
            sl[t] = w * al1[t];
            sr[t] = w * ar1[t];
        }
        __syncthreads();
        for (int off = 32; off > 0; off >>= 1) {
            if (t < 128 && (t & 63) < off) { sl[t] += sl[t+off]; sr[t] += sr[t+off]; }
            __syncthreads();
        }
        if (t < 128 && (t & 63) == 0) { d_c1[t>>6] = sl[t]; d_c1[2 + (t>>6)] = sr[t]; }
    }
}

// ---------------- bucket fill: single pass, no scan ----------------
__global__ void k_fillB(const int* __restrict__ src, const int* __restrict__ dst) {
    int e = blockIdx.x*blockDim.x + threadIdx.x;
    if (e >= NE) return;
    int d = dst[e];
    int p = atomicAdd(&d_cnt[d], 1);
    d_adjB[d*CAP + p] = src[e];
}

// ---------------- layer1 gather: per-node softmax sums -> t0,t1 (8 lanes/node) ---------
__global__ void k_e1g(const float* __restrict__ feat) {
    int t = blockIdx.x*blockDim.x + threadIdx.x;
    int node = t >> 3;
    int q = t & 7;
    bool valid = node < NN;
    int nn = valid ? node : 0;
    int cnt = valid ? d_cnt[nn] : 0;
    int base = nn*CAP;
    float fd = feat[nn];
    float B0 = d_c1[2]*fd, B1 = d_c1[3]*fd;
    float c0 = d_c1[0],   c1v = d_c1[1];
    float s0 = 0.f, n0 = 0.f, s1 = 0.f, n1 = 0.f;
    for (int j = q; j < cnt; j += 8) {
        int s = d_adjB[base + j];
        float fs = feat[s];
        float e0 = LRELU(fmaf(c0,  fs, B0));
        float e1 = LRELU(fmaf(c1v, fs, B1));
        float a0 = __expf(e0), a1 = __expf(e1);
        s0 += a0; n0 = fmaf(a0, fs, n0);
        s1 += a1; n1 = fmaf(a1, fs, n1);
    }
    #pragma unroll
    for (int o = 4; o > 0; o >>= 1) {
        s0 += __shfl_xor_sync(0xffffffffu, s0, o);
        n0 += __shfl_xor_sync(0xffffffffu, n0, o);
        s1 += __shfl_xor_sync(0xffffffffu, s1, o);
        n1 += __shfl_xor_sync(0xffffffffu, n1, o);
    }
    if (valid && q == 0) {
        float t0 = s0 > 0.f ? __fdividef(n0, s0) : 0.f;
        float t1 = s1 > 0.f ? __fdividef(n1, s1) : 0.f;
        d_t1[node] = make_float2(t0, t1);
    }
}

// ---------------- node kernel 1: 8 nodes/warp, packed-pair smem transpose, FFMA2 -------
// Block = 128 threads (4 warps). smem = 32KB sWR + 16KB sH = 48KB. (R11 measured-good.)
__global__ void __launch_bounds__(128) k_node1(
    const float* __restrict__ feat, const float* __restrict__ W1,
    const float* __restrict__ res1, const float* __restrict__ b1,
    const float* __restrict__ g1g, const float* __restrict__ g1b,
    const float* __restrict__ g1m, const float* __restrict__ g1v,
    const float* __restrict__ W2, const float* __restrict__ res2,
    const float* __restrict__ al2, const float* __restrict__ ar2)
{
    __shared__ float2 sWR[4096];                        // {W2,res2} interleaved  32KB
    __shared__ __align__(16) float2 sH[4][128*4];       // per-warp [k][pair]     16KB
    int tid = threadIdx.x;
    for (int i = tid; i < 4096; i += 128) sWR[i] = make_float2(W2[i], res2[i]);

    int lane = tid & 31;
    int warp = tid >> 5;
    float2* sHw = sH[warp];

    float Pq[4], Qq[4], Rq[4];
    #pragma unroll
    for (int q = 0; q < 4; q++) {
        int hd = lane + 32*q;
        float sc = g1g[hd] * rsqrtf(g1v[hd] + 1e-5f);
        Pq[q] = W1[hd]  * sc;
        Qq[q] = res1[hd]* sc;
        Rq[q] = fmaf(b1[hd] - g1m[hd], sc, g1b[hd]);
    }
    float al2l = al2[lane], ar2l = ar2[lane];
    __syncthreads();

    int wid  = blockIdx.x*4 + warp;          // grid 1184 -> 4736 warps
    int nwarp = gridDim.x*4;

    for (int base = wid*8; base < NN; base += nwarp*8) {   // NN = 8*6250, no tail
        int nl = base + (lane & 7);
        float f_l = feat[nl];
        float2 tt_l = d_t1[nl];
        float fm[8], t0m[8], t1m[8];
        #pragma unroll
        for (int m = 0; m < 8; m++) {
            fm[m]  = __shfl_sync(0xffffffffu, f_l,    m);
            t0m[m] = __shfl_sync(0xffffffffu, tt_l.x, m);
            t1m[m] = __shfl_sync(0xffffffffu, tt_l.y, m);
        }
        // phase A: lane owns k = lane + 32q; store packed node-pairs
        #pragma unroll
        for (int q = 0; q < 4; q++) {
            int k = lane + 32*q;
            #pragma unroll
            for (int p = 0; p < 4; p++) {
                float ta = (q < 2) ? t0m[2*p]   : t1m[2*p];
                float tb = (q < 2) ? t0m[2*p+1] : t1m[2*p+1];
                float ha = fmaxf(fmaf(Pq[q], ta, fmaf(Qq[q], fm[2*p],   Rq[q])), 0.f);
                float hb = fmaxf(fmaf(Pq[q], tb, fmaf(Qq[q], fm[2*p+1], Rq[q])), 0.f);
                sHw[k*4 + p] = make_float2(ha, hb);
            }
        }
        __syncwarp();

        // phase B: dual GEMV, 8 nodes, packed f32x2 accumulators
        unsigned long long F[4] = {0,0,0,0}, Rr[4] = {0,0,0,0};
        #pragma unroll 8
        for (int k = 0; k < 128; k++) {
            ulonglong2 hA = *(const ulonglong2*)&sHw[k*4];      // pairs (n0,n1),(n2,n3)
            ulonglong2 hB = *(const ulonglong2*)&sHw[k*4 + 2];  // pairs (n4,n5),(n6,n7)
            float2 wr = sWR[k*32 + lane];
            unsigned long long ww, rr;
            PACKF2(ww, wr.x, wr.x);
            PACKF2(rr, wr.y, wr.y);
            FMA_F32X2(F[0],  hA.x, ww);
            FMA_F32X2(F[1],  hA.y, ww);
            FMA_F32X2(F[2],  hB.x, ww);
            FMA_F32X2(F[3],  hB.y, ww);
            FMA_F32X2(Rr[0], hA.x, rr);
            FMA_F32X2(Rr[1], hA.y, rr);
            FMA_F32X2(Rr[2], hB.x, rr);
            FMA_F32X2(Rr[3], hB.y, rr);
        }
        __syncwarp();

        float f2[8], r2[8];
        #pragma unroll
        for (int p = 0; p < 4; p++) {
            UNPACKF2(f2[2*p], f2[2*p+1], F[p]);
            UNPACKF2(r2[2*p], r2[2*p+1], Rr[p]);
        }

        #pragma unroll
        for (int m = 0; m < 8; m++) {
            int n = base + m;
            d_feat2[n*32 + lane] = f2[m];
            d_res2p[n*32 + lane] = r2[m];
            float vl = f2[m]*al2l, vr = f2[m]*ar2l;
            #pragma unroll
            for (int o = 16; o > 0; o >>= 1) {
                vl += __shfl_xor_sync(0xffffffffu, vl, o);
                vr += __shfl_xor_sync(0xffffffffu, vr, o);
            }
            if (lane == 0) { d_el2[n] = vl; d_er2[n] = vr; }
        }
    }
}

// ---------------- layer2 gather + h2/BN2/ReLU: warp/node, 4x unrolled pipelined gather --
// Invalid lanes contribute a=0, sj=0 -> rounding trip count up to x4 is value-safe and
// lets the compiler issue 4 independent LDGs before the FMA chain (MLP=4).
__global__ void __launch_bounds__(256) k_e2h(
    const float* __restrict__ b2,
    const float* __restrict__ g2g, const float* __restrict__ g2b,
    const float* __restrict__ g2m, const float* __restrict__ g2v)
{
    int tid = threadIdx.x;
    int lane = tid & 31;
    int node = blockIdx.x*8 + (tid >> 5);    // grid 6250 -> exactly 50000 warps
    float sc2l = g2g[lane] * rsqrtf(g2v[lane] + 1e-5f);
    float sh2l = g2b[lane] - g2m[lane]*sc2l;
    float b2l  = b2[lane];

    int cnt = d_cnt[node];
    int base = node*CAP;
    float erd = d_er2[node];
    float acc = 0.f, la = 0.f;

    for (int c = 0; c < cnt; c += 32) {
        int j = c + lane;
        float a = 0.f; int sj = 0;
        if (j < cnt) {
            sj = d_adjB[base + j];
            float ev = LRELU(d_el2[sj] + erd);
            a = __expf(ev);
            la += a;
        }
        int m4 = (min(32, cnt - c) + 3) & ~3;     // round up; padded lanes add exact 0
        for (int k = 0; k < m4; k += 4) {
            float a0 = __shfl_sync(0xffffffffu, a, k);
            float a1 = __shfl_sync(0xffffffffu, a, k+1);
            float a2 = __shfl_sync(0xffffffffu, a, k+2);
            float a3 = __shfl_sync(0xffffffffu, a, k+3);
            int   s0 = __shfl_sync(0xffffffffu, sj, k);
            int   s1 = __shfl_sync(0xffffffffu, sj, k+1);
            int   s2 = __shfl_sync(0xffffffffu, sj, k+2);
            int   s3 = __shfl_sync(0xffffffffu, sj, k+3);
            float v0 = d_feat2[s0*32 + lane];
            float v1 = d_feat2[s1*32 + lane];
            float v2 = d_feat2[s2*32 + lane];
            float v3 = d_feat2[s3*32 + lane];
            acc = fmaf(a0, v0, acc);
            acc = fmaf(a1, v1, acc);
            acc = fmaf(a2, v2, acc);
            acc = fmaf(a3, v3, acc);
        }
    }
    #pragma unroll
    for (int o = 16; o > 0; o >>= 1) la += __shfl_xor_sync(0xffffffffu, la, o);

    float x = (la > 0.f ? __fdividef(acc, la) : 0.f) + d_res2p[node*32 + lane] + b2l;
    d_h2[node*32 + lane] = fmaxf(fmaf(x, sc2l, sh2l), 0.f);
}

// ---------------- decoder (4 nodes/warp) + merged graph mean-pool ----------------------
// Blocks [0,888): decoder. Blocks [888, 888+NG): pool for graph g = blockIdx-888.
__global__ void __launch_bounds__(256) k_node2d(
    const float* __restrict__ Wd1, const float* __restrict__ bd1,
    const float* __restrict__ gdg, const float* __restrict__ gdb,
    const float* __restrict__ gdm, const float* __restrict__ gdv,
    const float* __restrict__ Wd2, const float* __restrict__ bd2,
    const int* __restrict__ gids, float* __restrict__ out)
{
    int tid = threadIdx.x;
    int lane = tid & 31;

    if (blockIdx.x >= 888) {
        // ---- graph mean-pool (graph_ids sorted; binary-search bounds) ----
        int g = blockIdx.x - 888;
        int a = 0, b = NN;
        while (a < b) { int mid = (a+b) >> 1; if (gids[mid] < g) a = mid+1; else b = mid; }
        int lo = a;
        a = lo; b = NN;
        while (a < b) { int mid = (a+b) >> 1; if (gids[mid] < g+1) a = mid+1; else b = mid; }
        int hi = a;

        __shared__ float sacc[256];
        int grp = tid >> 5;
        float acc = 0.f;
        for (int n = lo + grp; n < hi; n += 8) acc += d_h2[n*32 + lane];
        sacc[tid] = acc;
        __syncthreads();
        if (tid < 128) sacc[tid] += sacc[tid + 128];
        __syncthreads();
        if (tid < 64)  sacc[tid] += sacc[tid + 64];
        __syncthreads();
        if (tid < 32) {
            float v = sacc[tid] + sacc[tid + 32];
            float cnt = (float)(hi - lo);
            out[g*32 + tid] = v / fmaxf(cnt, 1.f);
        }
        return;
    }

    __shared__ float4 sW4[32*32];   // Wd1 reordered: [k][lane] -> cols {lane,+32,+64,+96}
    for (int i = tid; i < 1024; i += 256) {
        int k = i >> 5, l = i & 31;
        sW4[i] = make_float4(Wd1[k*128 + l], Wd1[k*128 + l + 32],
                             Wd1[k*128 + l + 64], Wd1[k*128 + l + 96]);
    }
    float scd[4], shd[4], wd2l[4];
    #pragma unroll
    for (int j = 0; j < 4; j++) {
        int c = lane + 32*j;
        float sc = gdg[c] * rsqrtf(gdv[c] + 1e-5f);
        scd[j] = sc;
        shd[j] = fmaf(bd1[c] - gdm[c], sc, gdb[c]);
        wd2l[j] = Wd2[c];
    }
    float bd2v = bd2[0];
    __syncthreads();

    int wid  = blockIdx.x*8 + (tid >> 5);
    int nwarp = 888*8;

    for (int base = wid*4; base < NN; base += nwarp*4) {
        float h2v[4];
        #pragma unroll
        for (int m = 0; m < 4; m++) h2v[m] = d_h2[(base + m)*32 + lane];

        float y[4][4] = {{0,0,0,0},{0,0,0,0},{0,0,0,0},{0,0,0,0}};
        #pragma unroll 8
        for (int k = 0; k < 32; k++) {
            float4 w4 = sW4[k*32 + lane];
            #pragma unroll
            for (int m = 0; m < 4; m++) {
                float hk = __shfl_sync(0xffffffffu, h2v[m], k);
                y[m][0] = fmaf(hk, w4.x, y[m][0]);
                y[m][1] = fmaf(hk, w4.y, y[m][1]);
                y[m][2] = fmaf(hk, w4.z, y[m][2]);
                y[m][3] = fmaf(hk, w4.w, y[m][3]);
            }
        }
        #pragma unroll
        for (int m = 0; m < 4; m++) {
            float acc = 0.f;
            #pragma unroll
            for (int j = 0; j < 4; j++)
                acc += fmaxf(fmaf(y[m][j], scd[j], shd[j]), 0.f) * wd2l[j];
            #pragma unroll
            for (int o = 16; o > 0; o >>= 1) acc += __shfl_xor_sync(0xffffffffu, acc, o);
            if (lane == 0) out[2048 + base + m] = acc + bd2v;
        }
    }
}

// ---------------- launch ----------------
extern "C" void kernel_launch(void* const* d_in, const int* in_sizes, int n_in,
                              void* d_out, int out_size) {
    const float* feat = (const float*)d_in[0];
    const float* W1   = (const float*)d_in[1];
    const float* al1  = (const float*)d_in[2];
    const float* ar1  = (const float*)d_in[3];
    const float* res1 = (const float*)d_in[4];
    const float* b1   = (const float*)d_in[5];
    const float* g1g  = (const float*)d_in[6];
    const float* g1b  = (const float*)d_in[7];
    const float* g1m  = (const float*)d_in[8];
    const float* g1v  = (const float*)d_in[9];
    const float* W2   = (const float*)d_in[10];
    const float* al2  = (const float*)d_in[11];
    const float* ar2  = (const float*)d_in[12];
    const float* res2 = (const float*)d_in[13];
    const float* b2   = (const float*)d_in[14];
    const float* g2g  = (const float*)d_in[15];
    const float* g2b  = (const float*)d_in[16];
    const float* g2m  = (const float*)d_in[17];
    const float* g2v  = (const float*)d_in[18];
    const float* Wd1  = (const float*)d_in[19];
    const float* bd1  = (const float*)d_in[20];
    const float* gdg  = (const float*)d_in[21];
    const float* gdb  = (const float*)d_in[22];
    const float* gdm  = (const float*)d_in[23];
    const float* gdv  = (const float*)d_in[24];
    const float* Wd2  = (const float*)d_in[25];
    const float* bd2  = (const float*)d_in[26];
    const int* src    = (const int*)d_in[27];
    const int* dst    = (const int*)d_in[28];
    const int* gids   = (const int*)d_in[29];
    float* out = (float*)d_out;

    k_init<<<NBLK, 256>>>(W1, al1, ar1);
    k_fillB<<<(NE + 255)/256, 256>>>(src, dst);
    k_e1g<<<(NN*8 + 255)/256, 256>>>(feat);
    k_node1<<<1184, 128>>>(feat, W1, res1, b1, g1g, g1b, g1m, g1v, W2, res2, al2, ar2);
    k_e2h<<<NN/8, 256>>>(b2, g2g, g2b, g2m, g2v);
    k_node2d<<<888 + NG, 256>>>(Wd1, bd1, gdg, gdb, gdm, gdv, Wd2, bd2, gids, out);
}